// round 13
// baseline (speedup 1.0000x reference)
#include <cuda_runtime.h>
#include <math.h>

#define BN   8
#define HH   512
#define WW   1024
#define GG   104857
#define NTOT (BN * GG)          // 838856
#define NPIX (BN * HH * WW)     // 4194304
#define NPIX4 (NPIX / 4)        // 1048576

#define NB     592              // 148 SMs * 4 blocks -> all resident
#define NT     256
#define STRIDE (NB * NT)        // 151552
#define NPAIR  3                // 6 elements/thread (909312 >= NTOT)
#define NEL    (2 * NPAIR)

// ---------------- device scratch (no allocations allowed) ----------------
__device__ __align__(16) float2       g_pair[NPIX];   // (tgt, pred) interleaved, 33.5MB (L2-resident)
__device__ __align__(16) unsigned int g_hist8[256];   // top-8-bit counts
__device__ __align__(16) unsigned int g_cnt2[256];    // byte-2 counts (top8==b8)
__device__ __align__(16) float        g_fsum2[256];   // byte-2 sums   (top8==b8)
__device__ double       g_sum_valid;
__device__ double       g_sum_below;                  // Σ values with top8 < b8
__device__ unsigned int g_n;
__device__ unsigned int g_b8;
__device__ unsigned int g_k1;
__device__ unsigned int g_done0;                      // barrier-0 arrivals
__device__ unsigned int g_done1;                      // barrier-1 arrivals
__device__ unsigned int g_done2;                      // barrier-2 arrivals

// ---------------- fused persistent kernel ----------------
__global__ void __launch_bounds__(NT, 4)
fused_kernel(const float* __restrict__ pred,
             const float* __restrict__ tgt,
             const float* __restrict__ intr,
             const int*   __restrict__ p1,
             const int*   __restrict__ p2,
             const int*   __restrict__ p3,
             float* __restrict__ out)
{
    __shared__ unsigned int sh[256];
    __shared__ float        sh_f[256];
    __shared__ float        sh_red[8];
    __shared__ int          s_last;
    __shared__ unsigned int s_b8, s_k1;

    const float EPS   = 1e-6f;
    const float DCOS  = 0.867f;
    const float DDIFF = 0.005f;
    const float DZ    = 1e-5f;
    const float INF_F = __int_as_float(0x7f800000);

    int tid = threadIdx.x;
    int t   = blockIdx.x * NT + tid;

    sh[tid] = 0u;

    // ================= phase 0: interleave (tgt,pred) -> g_pair =================
    {
        const float4* t4 = reinterpret_cast<const float4*>(tgt);
        const float4* p4 = reinterpret_cast<const float4*>(pred);
        float4* o4 = reinterpret_cast<float4*>(g_pair);
        for (int q = t; q < NPIX4; q += STRIDE) {
            float4 a = t4[q];
            float4 b = p4[q];
            o4[2 * q]     = make_float4(a.x, b.x, a.y, b.y);
            o4[2 * q + 1] = make_float4(a.z, b.z, a.w, b.w);
        }
    }

    // ---- barrier 0: g_pair complete before gathers ----
    __threadfence();
    __syncthreads();
    if (tid == 0) {
        unsigned int v = atomicAdd(&g_done0, 1u);
        s_last = (v == NB - 1) ? 1 : 0;
    }
    __syncthreads();
    if (s_last) {
        if (tid == 0) {
            __threadfence();
            *((volatile unsigned int*)&g_done0) = 0u;   // release + replay reset
        }
    } else {
        if (tid == 0) {
            while (*((volatile unsigned int*)&g_done0) != 0u) __nanosleep(32);
            __threadfence();
        }
    }
    __syncthreads();

    // ================= phase 1: losses (kept in registers) =================
    float loss_r[NEL];
    float local_sum = 0.0f;

    #pragma unroll
    for (int p = 0; p < NPAIR; p++) {
        int  i0 = t + (2 * p)     * STRIDE;
        int  i1 = t + (2 * p + 1) * STRIDE;
        bool a0 = (i0 < NTOT), a1 = (i1 < NTOT);
        int  ii[2] = { a0 ? i0 : 0, a1 ? i1 : 0 };
        bool aa[2] = { a0, a1 };

        // batched front loads: 6 index loads + 6 float2 gathers in flight
        int    idx[2][3];
        float2 dv[2][3];
        #pragma unroll
        for (int r = 0; r < 2; r++) {
            idx[r][0] = __ldg(p1 + ii[r]);
            idx[r][1] = __ldg(p2 + ii[r]);
            idx[r][2] = __ldg(p3 + ii[r]);
        }
        #pragma unroll
        for (int r = 0; r < 2; r++) {
            int boff = (ii[r] / GG) * (HH * WW);
            #pragma unroll
            for (int j = 0; j < 3; j++)
                dv[r][j] = __ldg(g_pair + boff + idx[r][j]);
        }

        #pragma unroll
        for (int r = 0; r < 2; r++) {
            if (!aa[r]) { loss_r[2 * p + r] = -1.0f; continue; }   // sentinel: top8=0xBF
            int i = ii[r];
            int b = i / GG;
            float f    = __ldg(intr + b * 9 + 0);
            float u0   = __ldg(intr + b * 9 + 2);
            float v0   = __ldg(intr + b * 9 + 5);
            float invf = 1.0f / f;

            float Px[3], Py[3], Pz[3], Qx[3], Qy[3], Qz[3];
            #pragma unroll
            for (int j = 0; j < 3; j++) {
                int id  = idx[r][j];
                float u = (float)(id & (WW - 1)) - u0;
                float v = (float)(id >> 10)      - v0;
                float dt = dv[r][j].x, dp = dv[r][j].y;
                Px[j] = u * dt * invf;  Py[j] = v * dt * invf;  Pz[j] = dt;
                Qx[j] = u * dp * invf;  Qy[j] = v * dp * invf;  Qz[j] = dp;
            }

            // GT diffs: D0 = p2-p1, D1 = p3-p1, D2 = p3-p2
            float Dx[3], Dy[3], Dz[3];
            Dx[0] = Px[1] - Px[0]; Dy[0] = Py[1] - Py[0]; Dz[0] = Pz[1] - Pz[0];
            Dx[1] = Px[2] - Px[0]; Dy[1] = Py[2] - Py[0]; Dz[1] = Pz[2] - Pz[0];
            Dx[2] = Px[2] - Px[1]; Dy[2] = Py[2] - Py[1]; Dz[2] = Pz[2] - Pz[1];

            float e00 = Dx[0]*Dx[0] + Dy[0]*Dy[0] + Dz[0]*Dz[0];
            float e11 = Dx[1]*Dx[1] + Dy[1]*Dy[1] + Dz[1]*Dz[1];
            float e22 = Dx[2]*Dx[2] + Dy[2]*Dy[2] + Dz[2]*Dz[2];
            float e01 = Dx[0]*Dx[1] + Dy[0]*Dy[1] + Dz[0]*Dz[1];
            float e02 = Dx[0]*Dx[2] + Dy[0]*Dy[2] + Dz[0]*Dz[2];
            float e12 = Dx[1]*Dx[2] + Dy[1]*Dy[2] + Dz[1]*Dz[2];

            float p01 = sqrtf(e00 * e11);
            float p02 = sqrtf(e00 * e22);
            float p12 = sqrtf(e11 * e22);

            int cnt = 0;
            cnt += (e00 > DCOS * (e00 + EPS)) ? 1 : 0;
            cnt += (e11 > DCOS * (e11 + EPS)) ? 1 : 0;
            cnt += (e22 > DCOS * (e22 + EPS)) ? 1 : 0;
            cnt += (fabsf(e01) > DCOS * (p01 + EPS)) ? 2 : 0;
            cnt += (fabsf(e02) > DCOS * (p02 + EPS)) ? 2 : 0;
            cnt += (fabsf(e12) > DCOS * (p12 + EPS)) ? 2 : 0;
            bool mask_cos = cnt > 3;

            bool mask_pad = (Pz[0] > DZ) && (Pz[1] > DZ) && (Pz[2] > DZ);
            bool mx = (fabsf(Dx[0]) < DDIFF) || (fabsf(Dx[1]) < DDIFF) || (fabsf(Dx[2]) < DDIFF);
            bool my = (fabsf(Dy[0]) < DDIFF) || (fabsf(Dy[1]) < DDIFF) || (fabsf(Dy[2]) < DDIFF);
            bool mz = (fabsf(Dz[0]) < DDIFF) || (fabsf(Dz[1]) < DDIFF) || (fabsf(Dz[2]) < DDIFF);
            bool valid = mask_pad && !((mx && my && mz) || mask_cos);

            // faithful replication of pred_g[pred_g[:,:,2,:]==0] = 1e-4 broadcast quirk
            bool c0 = (Qz[0] == 0.0f), c1 = (Qz[1] == 0.0f), c2 = (Qz[2] == 0.0f);
            if (c0) { Qx[0] = 1e-4f; Qx[1] = 1e-4f; Qx[2] = 1e-4f; }
            if (c1) { Qy[0] = 1e-4f; Qy[1] = 1e-4f; Qy[2] = 1e-4f; }
            if (c2) { Qz[0] = 1e-4f; Qz[1] = 1e-4f; Qz[2] = 1e-4f; }

            float ngx = Dy[0] * Dz[1] - Dz[0] * Dy[1];
            float ngy = Dz[0] * Dx[1] - Dx[0] * Dz[1];
            float ngz = Dx[0] * Dy[1] - Dy[0] * Dx[1];
            float nng = sqrtf(ngx * ngx + ngy * ngy + ngz * ngz);
            if (nng == 0.0f) nng = EPS;
            float ig = 1.0f / nng;
            ngx *= ig; ngy *= ig; ngz *= ig;

            float ax = Qx[1] - Qx[0], ay = Qy[1] - Qy[0], az = Qz[1] - Qz[0];
            float bx = Qx[2] - Qx[0], by = Qy[2] - Qy[0], bz = Qz[2] - Qz[0];
            float npx = ay * bz - az * by;
            float npy = az * bx - ax * bz;
            float npz = ax * by - ay * bx;
            float nnp = sqrtf(npx * npx + npy * npy + npz * npz);
            if (nnp == 0.0f) nnp = EPS;
            float ip = 1.0f / nnp;
            npx *= ip; npy *= ip; npz *= ip;

            float loss = fabsf(ngx - npx) + fabsf(ngy - npy) + fabsf(ngz - npz);

            float o = valid ? loss : INF_F;
            loss_r[2 * p + r] = o;
            if (valid) local_sum += loss;
            atomicAdd(&sh[__float_as_uint(o) >> 24], 1u);
        }
    }

    // block reduction of valid-sum
    {
        float s = local_sum;
        #pragma unroll
        for (int o = 16; o > 0; o >>= 1)
            s += __shfl_down_sync(0xffffffffu, s, o);
        if ((tid & 31) == 0) sh_red[tid >> 5] = s;
        __syncthreads();
        if (tid == 0) {
            float ts = 0.0f;
            #pragma unroll
            for (int w = 0; w < 8; w++) ts += sh_red[w];
            atomicAdd(&g_sum_valid, (double)ts);
        }
    }
    {
        unsigned int h = sh[tid];
        if (h) atomicAdd(&g_hist8[tid], h);
    }

    // ================= barrier 1 (+ resolve b8 in last block) =================
    __threadfence();
    __syncthreads();
    if (tid == 0) {
        unsigned int v = atomicAdd(&g_done1, 1u);
        s_last = (v == NB - 1) ? 1 : 0;
    }
    __syncthreads();

    if (s_last) {
        volatile unsigned int* vh = (volatile unsigned int*)g_hist8;
        unsigned int c = vh[tid];
        __shared__ unsigned int rs[256];
        __shared__ unsigned int rs_n;
        if (tid == 0x7f) rs_n = NTOT - c;  // +inf top8 = 0x7f; finite = valid
        rs[tid] = c;
        __syncthreads();
        #pragma unroll
        for (int o = 1; o < 256; o <<= 1) {
            unsigned int v = (tid >= o) ? rs[tid - o] : 0u;
            __syncthreads();
            rs[tid] += v;
            __syncthreads();
        }
        unsigned int n = rs_n;
        unsigned int k = n >> 2;
        if (tid == 0) {
            g_n = n;
            if (k == 0) { g_b8 = 0u; g_k1 = 0u; }
        }
        if (k > 0) {
            unsigned int below = (tid > 0) ? rs[tid - 1] : 0u;
            if (rs[tid] >= k && below < k) { g_b8 = (unsigned int)tid; g_k1 = k - below; }
        }
        __syncthreads();
        if (tid == 0) {
            __threadfence();
            *((volatile unsigned int*)&g_done1) = 0u;
        }
    } else {
        if (tid == 0) {
            while (*((volatile unsigned int*)&g_done1) != 0u) __nanosleep(64);
            __threadfence();
        }
    }
    __syncthreads();
    if (tid == 0) {
        s_b8 = *((volatile unsigned int*)&g_b8);
        s_k1 = *((volatile unsigned int*)&g_k1);
    }
    sh[tid]   = 0u;
    sh_f[tid] = 0.0f;
    __syncthreads();

    // ================= phase 2: Σ_below + byte-2 hist from registers =================
    unsigned int b8 = s_b8;
    float sb = 0.0f;
    #pragma unroll
    for (int e = 0; e < NEL; e++) {
        float val = loss_r[e];
        unsigned int bits = __float_as_uint(val);
        unsigned int top = bits >> 24;
        if (top < b8) {
            sb += val;
        } else if (top == b8) {
            unsigned int bj = (bits >> 16) & 0xffu;
            atomicAdd(&sh[bj], 1u);
            atomicAdd(&sh_f[bj], val);
        }
    }
    {
        #pragma unroll
        for (int o = 16; o > 0; o >>= 1)
            sb += __shfl_down_sync(0xffffffffu, sb, o);
        if ((tid & 31) == 0) sh_red[tid >> 5] = sb;
        __syncthreads();
        if (tid == 0) {
            float tb = 0.0f;
            #pragma unroll
            for (int w = 0; w < 8; w++) tb += sh_red[w];
            atomicAdd(&g_sum_below, (double)tb);
        }
    }
    {
        unsigned int hc = sh[tid];
        if (hc) {
            atomicAdd(&g_cnt2[tid], hc);
            atomicAdd(&g_fsum2[tid], sh_f[tid]);
        }
    }

    // ================= barrier 2 (+ finish in last block) =================
    __threadfence();
    __syncthreads();
    if (tid == 0) {
        unsigned int v = atomicAdd(&g_done2, 1u);
        s_last = (v == NB - 1) ? 1 : 0;
    }
    __syncthreads();

    if (!s_last) {
        if (tid == 0) {
            while (*((volatile unsigned int*)&g_done2) != 0u) __nanosleep(64);
        }
        return;
    }

    // ---- finish: pick byte-2 bin, assemble scalar ----
    {
        volatile unsigned int* vc = (volatile unsigned int*)g_cnt2;
        volatile float*        vf = (volatile float*)g_fsum2;
        unsigned int c = vc[tid];
        float        fv = vf[tid];
        __shared__ unsigned int s_scan[256];
        __shared__ int          s_j;
        __shared__ unsigned int s_cum;
        s_scan[tid] = c;
        sh_f[tid]   = fv;
        if (tid == 0) { s_j = 0; s_cum = 0u; }
        __syncthreads();

        #pragma unroll
        for (int o = 1; o < 256; o <<= 1) {
            unsigned int v = (tid >= o) ? s_scan[tid - o] : 0u;
            __syncthreads();
            s_scan[tid] += v;
            __syncthreads();
        }

        unsigned int k1 = s_k1;
        if (k1 > 0) {
            unsigned int below = (tid > 0) ? s_scan[tid - 1] : 0u;
            if (s_scan[tid] >= k1 && below < k1) { s_j = tid; s_cum = below; }
        }
        __syncthreads();

        int j = s_j;
        float x = (tid < j) ? sh_f[tid] : 0.0f;
        #pragma unroll
        for (int o = 16; o > 0; o >>= 1)
            x += __shfl_down_sync(0xffffffffu, x, o);
        if ((tid & 31) == 0) sh_red[tid >> 5] = x;
        __syncthreads();

        if (tid == 0) {
            float sum_full = 0.0f;
            #pragma unroll
            for (int w = 0; w < 8; w++) sum_full += sh_red[w];

            double sv  = *((volatile double*)&g_sum_valid);
            double sbd = *((volatile double*)&g_sum_below);
            unsigned int n = *((volatile unsigned int*)&g_n);

            float tf = __uint_as_float((s_b8 << 24) | ((unsigned int)j << 16));
            double sum_small = sbd + (double)sum_full
                             + (double)(k1 - s_cum) * (double)tf;
            long long d = (long long)n - (long long)(n >> 2);
            if (d < 1) d = 1;
            out[0] = (float)((sv - sum_small) / (double)d);
        }
    }
    __syncthreads();

    // reset all scratch, then release barrier 2 (leaves clean state for replay)
    g_hist8[tid] = 0u;
    g_cnt2[tid]  = 0u;
    g_fsum2[tid] = 0.0f;
    if (tid == 0) { g_sum_valid = 0.0; g_sum_below = 0.0; }
    __syncthreads();
    if (tid == 0) {
        __threadfence();
        *((volatile unsigned int*)&g_done2) = 0u;
    }
}

// ---------------- launch ----------------
extern "C" void kernel_launch(void* const* d_in, const int* in_sizes, int n_in,
                              void* d_out, int out_size)
{
    const float* pred = (const float*)d_in[0];
    const float* tgt  = (const float*)d_in[1];
    // d_in[2] = mask (already baked into p1/p2/p3; unused)
    const float* intr = (const float*)d_in[3];
    const int*   p1   = (const int*)d_in[4];
    const int*   p2   = (const int*)d_in[5];
    const int*   p3   = (const int*)d_in[6];
    float* out = (float*)d_out;

    fused_kernel<<<NB, NT>>>(pred, tgt, intr, p1, p2, p3, out);
}

// round 14
// speedup vs baseline: 1.1267x; 1.1267x over previous
#include <cuda_runtime.h>
#include <math.h>

#define BN   8
#define HH   512
#define WW   1024
#define GG   104857
#define NTOT (BN * GG)          // 838856

#define NB     444              // 148 SMs * 3 blocks -> all resident (regs<=85)
#define NT     256
#define STRIDE (NB * NT)        // 113664
#define NPAIR  4                // 8 elements/thread (909312 >= NTOT)
#define NEL    (2 * NPAIR)

// ---------------- device scratch (no allocations allowed) ----------------
__device__ __align__(16) unsigned int g_hist8[256];   // top-8-bit counts
__device__ __align__(16) unsigned int g_cnt2[256];    // byte-2 counts (top8==b8)
__device__ __align__(16) float        g_fsum2[256];   // byte-2 sums   (top8==b8)
__device__ double       g_sum_valid;
__device__ double       g_sum_below;                  // Σ values with top8 < b8
__device__ unsigned int g_n;
__device__ unsigned int g_b8;
__device__ unsigned int g_k1;
__device__ unsigned int g_done1;                      // barrier-1 arrivals
__device__ unsigned int g_done2;                      // barrier-2 arrivals

// ---------------- fused persistent kernel ----------------
__global__ void __launch_bounds__(NT, 3)
fused_kernel(const float* __restrict__ pred,
             const float* __restrict__ tgt,
             const float* __restrict__ intr,
             const int*   __restrict__ p1,
             const int*   __restrict__ p2,
             const int*   __restrict__ p3,
             float* __restrict__ out)
{
    __shared__ unsigned int sh[256];
    __shared__ float        sh_f[256];
    __shared__ float        sh_red[8];
    __shared__ int          s_last;
    __shared__ unsigned int s_b8, s_k1;

    const float EPS   = 1e-6f;
    const float DCOS  = 0.867f;
    const float DDIFF = 0.005f;
    const float DZ    = 1e-5f;
    const float INF_F = __int_as_float(0x7f800000);

    int tid = threadIdx.x;
    int t   = blockIdx.x * NT + tid;

    sh[tid] = 0u;
    __syncthreads();

    // ================= phase 1: losses (software-pipelined pairs) =================
    float loss_r[NEL];
    float local_sum = 0.0f;

    // double buffers
    int   idxA[2][3], idxB[2][3];
    float dtA[2][3],  dtB[2][3];
    float dpA[2][3],  dpB[2][3];

    auto load_pair = [&](int p, int (&idx)[2][3], float (&dt)[2][3], float (&dp)[2][3]) {
        int  i0 = t + (2 * p)     * STRIDE;
        int  i1 = t + (2 * p + 1) * STRIDE;
        int  ii[2] = { (i0 < NTOT) ? i0 : 0, (i1 < NTOT) ? i1 : 0 };
        #pragma unroll
        for (int r = 0; r < 2; r++) {
            idx[r][0] = __ldg(p1 + ii[r]);
            idx[r][1] = __ldg(p2 + ii[r]);
            idx[r][2] = __ldg(p3 + ii[r]);
        }
        #pragma unroll
        for (int r = 0; r < 2; r++) {
            int boff = (ii[r] / GG) * (HH * WW);
            #pragma unroll
            for (int j = 0; j < 3; j++) {
                dt[r][j] = __ldg(tgt  + boff + idx[r][j]);
                dp[r][j] = __ldg(pred + boff + idx[r][j]);
            }
        }
    };

    auto compute_pair = [&](int p, int (&idx)[2][3], float (&dt)[2][3], float (&dp)[2][3]) {
        #pragma unroll
        for (int r = 0; r < 2; r++) {
            int  i = t + (2 * p + r) * STRIDE;
            if (i >= NTOT) { loss_r[2 * p + r] = -1.0f; continue; }  // sentinel: top8=0xBF
            int b = i / GG;
            float f    = __ldg(intr + b * 9 + 0);
            float u0   = __ldg(intr + b * 9 + 2);
            float v0   = __ldg(intr + b * 9 + 5);
            float invf = 1.0f / f;

            float Px[3], Py[3], Pz[3], Qx[3], Qy[3], Qz[3];
            #pragma unroll
            for (int j = 0; j < 3; j++) {
                int id  = idx[r][j];
                float u = (float)(id & (WW - 1)) - u0;
                float v = (float)(id >> 10)      - v0;
                float dtv = dt[r][j], dpv = dp[r][j];
                Px[j] = u * dtv * invf;  Py[j] = v * dtv * invf;  Pz[j] = dtv;
                Qx[j] = u * dpv * invf;  Qy[j] = v * dpv * invf;  Qz[j] = dpv;
            }

            // GT diffs: D0 = p2-p1, D1 = p3-p1, D2 = p3-p2
            float Dx[3], Dy[3], Dz[3];
            Dx[0] = Px[1] - Px[0]; Dy[0] = Py[1] - Py[0]; Dz[0] = Pz[1] - Pz[0];
            Dx[1] = Px[2] - Px[0]; Dy[1] = Py[2] - Py[0]; Dz[1] = Pz[2] - Pz[0];
            Dx[2] = Px[2] - Px[1]; Dy[2] = Py[2] - Py[1]; Dz[2] = Pz[2] - Pz[1];

            float e00 = Dx[0]*Dx[0] + Dy[0]*Dy[0] + Dz[0]*Dz[0];
            float e11 = Dx[1]*Dx[1] + Dy[1]*Dy[1] + Dz[1]*Dz[1];
            float e22 = Dx[2]*Dx[2] + Dy[2]*Dy[2] + Dz[2]*Dz[2];
            float e01 = Dx[0]*Dx[1] + Dy[0]*Dy[1] + Dz[0]*Dz[1];
            float e02 = Dx[0]*Dx[2] + Dy[0]*Dy[2] + Dz[0]*Dz[2];
            float e12 = Dx[1]*Dx[2] + Dy[1]*Dy[2] + Dz[1]*Dz[2];

            float p01 = sqrtf(e00 * e11);
            float p02 = sqrtf(e00 * e22);
            float p12 = sqrtf(e11 * e22);

            int cnt = 0;
            cnt += (e00 > DCOS * (e00 + EPS)) ? 1 : 0;
            cnt += (e11 > DCOS * (e11 + EPS)) ? 1 : 0;
            cnt += (e22 > DCOS * (e22 + EPS)) ? 1 : 0;
            cnt += (fabsf(e01) > DCOS * (p01 + EPS)) ? 2 : 0;
            cnt += (fabsf(e02) > DCOS * (p02 + EPS)) ? 2 : 0;
            cnt += (fabsf(e12) > DCOS * (p12 + EPS)) ? 2 : 0;
            bool mask_cos = cnt > 3;

            bool mask_pad = (Pz[0] > DZ) && (Pz[1] > DZ) && (Pz[2] > DZ);
            bool mx = (fabsf(Dx[0]) < DDIFF) || (fabsf(Dx[1]) < DDIFF) || (fabsf(Dx[2]) < DDIFF);
            bool my = (fabsf(Dy[0]) < DDIFF) || (fabsf(Dy[1]) < DDIFF) || (fabsf(Dy[2]) < DDIFF);
            bool mz = (fabsf(Dz[0]) < DDIFF) || (fabsf(Dz[1]) < DDIFF) || (fabsf(Dz[2]) < DDIFF);
            bool valid = mask_pad && !((mx && my && mz) || mask_cos);

            // faithful replication of pred_g[pred_g[:,:,2,:]==0] = 1e-4 broadcast quirk
            bool c0 = (Qz[0] == 0.0f), c1 = (Qz[1] == 0.0f), c2 = (Qz[2] == 0.0f);
            if (c0) { Qx[0] = 1e-4f; Qx[1] = 1e-4f; Qx[2] = 1e-4f; }
            if (c1) { Qy[0] = 1e-4f; Qy[1] = 1e-4f; Qy[2] = 1e-4f; }
            if (c2) { Qz[0] = 1e-4f; Qz[1] = 1e-4f; Qz[2] = 1e-4f; }

            float ngx = Dy[0] * Dz[1] - Dz[0] * Dy[1];
            float ngy = Dz[0] * Dx[1] - Dx[0] * Dz[1];
            float ngz = Dx[0] * Dy[1] - Dy[0] * Dx[1];
            float nng = sqrtf(ngx * ngx + ngy * ngy + ngz * ngz);
            if (nng == 0.0f) nng = EPS;
            float ig = 1.0f / nng;
            ngx *= ig; ngy *= ig; ngz *= ig;

            float ax = Qx[1] - Qx[0], ay = Qy[1] - Qy[0], az = Qz[1] - Qz[0];
            float bx = Qx[2] - Qx[0], by = Qy[2] - Qy[0], bz = Qz[2] - Qz[0];
            float npx = ay * bz - az * by;
            float npy = az * bx - ax * bz;
            float npz = ax * by - ay * bx;
            float nnp = sqrtf(npx * npx + npy * npy + npz * npz);
            if (nnp == 0.0f) nnp = EPS;
            float ip = 1.0f / nnp;
            npx *= ip; npy *= ip; npz *= ip;

            float loss = fabsf(ngx - npx) + fabsf(ngy - npy) + fabsf(ngz - npz);

            float o = valid ? loss : INF_F;
            loss_r[2 * p + r] = o;
            if (valid) local_sum += loss;
            atomicAdd(&sh[__float_as_uint(o) >> 24], 1u);
        }
    };

    // pipelined schedule: load p+1 before computing p (fully unrolled)
    load_pair(0, idxA, dtA, dpA);
    load_pair(1, idxB, dtB, dpB);
    compute_pair(0, idxA, dtA, dpA);
    load_pair(2, idxA, dtA, dpA);
    compute_pair(1, idxB, dtB, dpB);
    load_pair(3, idxB, dtB, dpB);
    compute_pair(2, idxA, dtA, dpA);
    compute_pair(3, idxB, dtB, dpB);

    // block reduction of valid-sum
    {
        float s = local_sum;
        #pragma unroll
        for (int o = 16; o > 0; o >>= 1)
            s += __shfl_down_sync(0xffffffffu, s, o);
        if ((tid & 31) == 0) sh_red[tid >> 5] = s;
        __syncthreads();
        if (tid == 0) {
            float ts = 0.0f;
            #pragma unroll
            for (int w = 0; w < 8; w++) ts += sh_red[w];
            atomicAdd(&g_sum_valid, (double)ts);
        }
    }
    {
        unsigned int h = sh[tid];
        if (h) atomicAdd(&g_hist8[tid], h);
    }

    // ================= barrier 1 (+ resolve b8 in last block) =================
    __threadfence();
    __syncthreads();
    if (tid == 0) {
        unsigned int v = atomicAdd(&g_done1, 1u);
        s_last = (v == NB - 1) ? 1 : 0;
    }
    __syncthreads();

    if (s_last) {
        volatile unsigned int* vh = (volatile unsigned int*)g_hist8;
        unsigned int c = vh[tid];
        __shared__ unsigned int rs[256];
        __shared__ unsigned int rs_n;
        if (tid == 0x7f) rs_n = NTOT - c;  // +inf top8 = 0x7f; finite = valid
        rs[tid] = c;
        __syncthreads();
        #pragma unroll
        for (int o = 1; o < 256; o <<= 1) {
            unsigned int v = (tid >= o) ? rs[tid - o] : 0u;
            __syncthreads();
            rs[tid] += v;
            __syncthreads();
        }
        unsigned int n = rs_n;
        unsigned int k = n >> 2;
        if (tid == 0) {
            g_n = n;
            if (k == 0) { g_b8 = 0u; g_k1 = 0u; }
        }
        if (k > 0) {
            unsigned int below = (tid > 0) ? rs[tid - 1] : 0u;
            if (rs[tid] >= k && below < k) { g_b8 = (unsigned int)tid; g_k1 = k - below; }
        }
        __syncthreads();
        if (tid == 0) {
            __threadfence();
            *((volatile unsigned int*)&g_done1) = 0u;   // release (also resets for replay)
        }
    } else {
        if (tid == 0) {
            while (*((volatile unsigned int*)&g_done1) != 0u) __nanosleep(64);
            __threadfence();
        }
    }
    __syncthreads();
    if (tid == 0) {
        s_b8 = *((volatile unsigned int*)&g_b8);
        s_k1 = *((volatile unsigned int*)&g_k1);
    }
    sh[tid]   = 0u;
    sh_f[tid] = 0.0f;
    __syncthreads();

    // ================= phase 2: Σ_below + byte-2 hist from registers =================
    unsigned int b8 = s_b8;
    float sb = 0.0f;
    #pragma unroll
    for (int e = 0; e < NEL; e++) {
        float val = loss_r[e];
        unsigned int bits = __float_as_uint(val);
        unsigned int top = bits >> 24;      // sentinel 0xBF and +inf 0x7f self-exclude
        if (top < b8) {
            sb += val;
        } else if (top == b8) {
            unsigned int bj = (bits >> 16) & 0xffu;
            atomicAdd(&sh[bj], 1u);
            atomicAdd(&sh_f[bj], val);
        }
    }
    {
        #pragma unroll
        for (int o = 16; o > 0; o >>= 1)
            sb += __shfl_down_sync(0xffffffffu, sb, o);
        if ((tid & 31) == 0) sh_red[tid >> 5] = sb;
        __syncthreads();
        if (tid == 0) {
            float tb = 0.0f;
            #pragma unroll
            for (int w = 0; w < 8; w++) tb += sh_red[w];
            atomicAdd(&g_sum_below, (double)tb);
        }
    }
    {
        unsigned int hc = sh[tid];
        if (hc) {
            atomicAdd(&g_cnt2[tid], hc);
            atomicAdd(&g_fsum2[tid], sh_f[tid]);
        }
    }

    // ================= barrier 2 (+ finish in last block) =================
    __threadfence();
    __syncthreads();
    if (tid == 0) {
        unsigned int v = atomicAdd(&g_done2, 1u);
        s_last = (v == NB - 1) ? 1 : 0;
    }
    __syncthreads();

    if (!s_last) {
        if (tid == 0) {
            while (*((volatile unsigned int*)&g_done2) != 0u) __nanosleep(64);
        }
        return;
    }

    // ---- finish: pick byte-2 bin, assemble scalar ----
    {
        volatile unsigned int* vc = (volatile unsigned int*)g_cnt2;
        volatile float*        vf = (volatile float*)g_fsum2;
        unsigned int c = vc[tid];
        float        fv = vf[tid];
        __shared__ unsigned int s_scan[256];
        __shared__ int          s_j;
        __shared__ unsigned int s_cum;
        s_scan[tid] = c;
        sh_f[tid]   = fv;
        if (tid == 0) { s_j = 0; s_cum = 0u; }
        __syncthreads();

        #pragma unroll
        for (int o = 1; o < 256; o <<= 1) {
            unsigned int v = (tid >= o) ? s_scan[tid - o] : 0u;
            __syncthreads();
            s_scan[tid] += v;
            __syncthreads();
        }

        unsigned int k1 = s_k1;
        if (k1 > 0) {
            unsigned int below = (tid > 0) ? s_scan[tid - 1] : 0u;
            if (s_scan[tid] >= k1 && below < k1) { s_j = tid; s_cum = below; }
        }
        __syncthreads();

        int j = s_j;
        float x = (tid < j) ? sh_f[tid] : 0.0f;
        #pragma unroll
        for (int o = 16; o > 0; o >>= 1)
            x += __shfl_down_sync(0xffffffffu, x, o);
        if ((tid & 31) == 0) sh_red[tid >> 5] = x;
        __syncthreads();

        if (tid == 0) {
            float sum_full = 0.0f;
            #pragma unroll
            for (int w = 0; w < 8; w++) sum_full += sh_red[w];

            double sv  = *((volatile double*)&g_sum_valid);
            double sbd = *((volatile double*)&g_sum_below);
            unsigned int n = *((volatile unsigned int*)&g_n);

            // partial bin priced at its lower edge (error << 1e-3 relative)
            float tf = __uint_as_float((s_b8 << 24) | ((unsigned int)j << 16));
            double sum_small = sbd + (double)sum_full
                             + (double)(k1 - s_cum) * (double)tf;
            long long d = (long long)n - (long long)(n >> 2);
            if (d < 1) d = 1;
            out[0] = (float)((sv - sum_small) / (double)d);
        }
    }
    __syncthreads();

    // reset all scratch, then release barrier 2 (leaves clean state for replay)
    g_hist8[tid] = 0u;
    g_cnt2[tid]  = 0u;
    g_fsum2[tid] = 0.0f;
    if (tid == 0) { g_sum_valid = 0.0; g_sum_below = 0.0; }
    __syncthreads();
    if (tid == 0) {
        __threadfence();
        *((volatile unsigned int*)&g_done2) = 0u;
    }
}

// ---------------- launch ----------------
extern "C" void kernel_launch(void* const* d_in, const int* in_sizes, int n_in,
                              void* d_out, int out_size)
{
    const float* pred = (const float*)d_in[0];
    const float* tgt  = (const float*)d_in[1];
    // d_in[2] = mask (already baked into p1/p2/p3; unused)
    const float* intr = (const float*)d_in[3];
    const int*   p1   = (const int*)d_in[4];
    const int*   p2   = (const int*)d_in[5];
    const int*   p3   = (const int*)d_in[6];
    float* out = (float*)d_out;

    fused_kernel<<<NB, NT>>>(pred, tgt, intr, p1, p2, p3, out);
}

// round 15
// speedup vs baseline: 1.2656x; 1.1233x over previous
#include <cuda_runtime.h>
#include <math.h>

#define BN   8
#define HH   512
#define WW   1024
#define GG   104857
#define NTOT (BN * GG)          // 838856
#define NQUAD (NTOT / 4)        // 209714
#define NHALF (NTOT / 2)        // 419428

#define CK_BLOCKS ((NHALF + 255) / 256)   // 1639
#define PC_BLOCKS 205
#define PC_STRIDE (PC_BLOCKS * 256)       // 52480

// ---------------- device scratch (no allocations allowed) ----------------
// Zero at module load; the passC last-block epilogue re-zeroes everything at
// the end of every run, so each kernel_launch starts from a clean state.
__device__ __align__(16) float        g_loss[NTOT];
__device__ __align__(16) unsigned int g_hist8[256];   // top-8-bit counts
__device__ __align__(16) unsigned int g_cnt2[256];    // byte-2 counts (top8==b8)
__device__ __align__(16) float        g_fsum2[256];   // byte-2 sums   (top8==b8)
__device__ double       g_sum_valid;
__device__ double       g_sum_below;                  // Σ values with top8 < b8
__device__ unsigned int g_n;
__device__ unsigned int g_b8;
__device__ unsigned int g_k1;
__device__ unsigned int g_done1;                      // compute blocks retired
__device__ unsigned int g_done2;                      // passC blocks retired

// ---------------- compute: loss + Σ_valid + top-8 hist; last block resolves b8 ----------------
__global__ void __launch_bounds__(256)
compute_kernel(const float* __restrict__ pred,
               const float* __restrict__ tgt,
               const float* __restrict__ intr,
               const int*   __restrict__ p1,
               const int*   __restrict__ p2,
               const int*   __restrict__ p3)
{
    __shared__ unsigned int sh[256];
    __shared__ float        sh_sum[8];
    __shared__ int          s_last;
    sh[threadIdx.x] = 0u;
    __syncthreads();

    const float EPS   = 1e-6f;
    const float DCOS  = 0.867f;
    const float DDIFF = 0.005f;
    const float DZ    = 1e-5f;
    const float INF_F = __int_as_float(0x7f800000);

    float local_sum = 0.0f;

    int t = blockIdx.x * blockDim.x + threadIdx.x;
    bool active = (t < NHALF);           // BOTH elements valid iff t < NHALF

    // ---- batched front loads for both elements (max MLP) ----
    int   idx[2][3];
    float dtv[2][3], dpv[2][3];
    int   ii[2] = { active ? t : 0, active ? t + NHALF : 0 };

    #pragma unroll
    for (int r = 0; r < 2; r++) {
        idx[r][0] = __ldg(p1 + ii[r]);
        idx[r][1] = __ldg(p2 + ii[r]);
        idx[r][2] = __ldg(p3 + ii[r]);
    }
    #pragma unroll
    for (int r = 0; r < 2; r++) {
        int b = ii[r] / GG;
        const float* tb = tgt  + b * (HH * WW);
        const float* pb = pred + b * (HH * WW);
        #pragma unroll
        for (int j = 0; j < 3; j++) {
            // L2-only gathers: random 4B over 16MB -> L1 allocation is pure overhead
            dtv[r][j] = __ldcg(tb + idx[r][j]);
            dpv[r][j] = __ldcg(pb + idx[r][j]);
        }
    }

    #pragma unroll
    for (int r = 0; r < 2; r++) {
        if (!active) continue;
        int i = ii[r];
        int b = i / GG;
        float f    = __ldg(intr + b * 9 + 0);
        float u0   = __ldg(intr + b * 9 + 2);
        float v0   = __ldg(intr + b * 9 + 5);
        float invf = 1.0f / f;

        float Px[3], Py[3], Pz[3], Qx[3], Qy[3], Qz[3];
        #pragma unroll
        for (int j = 0; j < 3; j++) {
            int id  = idx[r][j];
            float u = (float)(id & (WW - 1)) - u0;
            float v = (float)(id >> 10)      - v0;
            float dt = dtv[r][j], dp = dpv[r][j];
            Px[j] = u * dt * invf;  Py[j] = v * dt * invf;  Pz[j] = dt;
            Qx[j] = u * dp * invf;  Qy[j] = v * dp * invf;  Qz[j] = dp;
        }

        // GT diffs: D0 = p2-p1, D1 = p3-p1, D2 = p3-p2
        float Dx[3], Dy[3], Dz[3];
        Dx[0] = Px[1] - Px[0]; Dy[0] = Py[1] - Py[0]; Dz[0] = Pz[1] - Pz[0];
        Dx[1] = Px[2] - Px[0]; Dy[1] = Py[2] - Py[0]; Dz[1] = Pz[2] - Pz[0];
        Dx[2] = Px[2] - Px[1]; Dy[2] = Py[2] - Py[1]; Dz[2] = Pz[2] - Pz[1];

        // Gram matrix of diffs (symmetric)
        float e00 = Dx[0]*Dx[0] + Dy[0]*Dy[0] + Dz[0]*Dz[0];
        float e11 = Dx[1]*Dx[1] + Dy[1]*Dy[1] + Dz[1]*Dz[1];
        float e22 = Dx[2]*Dx[2] + Dy[2]*Dy[2] + Dz[2]*Dz[2];
        float e01 = Dx[0]*Dx[1] + Dy[0]*Dy[1] + Dz[0]*Dz[1];
        float e02 = Dx[0]*Dx[2] + Dy[0]*Dy[2] + Dz[0]*Dz[2];
        float e12 = Dx[1]*Dx[2] + Dy[1]*Dy[2] + Dz[1]*Dz[2];

        // diag: qn_i*qn_i == e_ii ; off-diag: qn_i*qn_j == sqrt(e_ii*e_jj)
        float p01 = sqrtf(e00 * e11);
        float p02 = sqrtf(e00 * e22);
        float p12 = sqrtf(e11 * e22);

        int cnt = 0;
        cnt += (e00 > DCOS * (e00 + EPS)) ? 1 : 0;
        cnt += (e11 > DCOS * (e11 + EPS)) ? 1 : 0;
        cnt += (e22 > DCOS * (e22 + EPS)) ? 1 : 0;
        cnt += (fabsf(e01) > DCOS * (p01 + EPS)) ? 2 : 0;
        cnt += (fabsf(e02) > DCOS * (p02 + EPS)) ? 2 : 0;
        cnt += (fabsf(e12) > DCOS * (p12 + EPS)) ? 2 : 0;
        bool mask_cos = cnt > 3;

        bool mask_pad = (Pz[0] > DZ) && (Pz[1] > DZ) && (Pz[2] > DZ);
        bool mx = (fabsf(Dx[0]) < DDIFF) || (fabsf(Dx[1]) < DDIFF) || (fabsf(Dx[2]) < DDIFF);
        bool my = (fabsf(Dy[0]) < DDIFF) || (fabsf(Dy[1]) < DDIFF) || (fabsf(Dy[2]) < DDIFF);
        bool mz = (fabsf(Dz[0]) < DDIFF) || (fabsf(Dz[1]) < DDIFF) || (fabsf(Dz[2]) < DDIFF);
        bool valid = mask_pad && !((mx && my && mz) || mask_cos);

        // faithful replication of pred_g[pred_g[:,:,2,:]==0] = 1e-4 broadcast quirk:
        // z of point j == 0  =>  coord j of ALL points := 1e-4
        bool c0 = (Qz[0] == 0.0f), c1 = (Qz[1] == 0.0f), c2 = (Qz[2] == 0.0f);
        if (c0) { Qx[0] = 1e-4f; Qx[1] = 1e-4f; Qx[2] = 1e-4f; }
        if (c1) { Qy[0] = 1e-4f; Qy[1] = 1e-4f; Qy[2] = 1e-4f; }
        if (c2) { Qz[0] = 1e-4f; Qz[1] = 1e-4f; Qz[2] = 1e-4f; }

        // GT normal: cross(D0, D1)
        float ngx = Dy[0] * Dz[1] - Dz[0] * Dy[1];
        float ngy = Dz[0] * Dx[1] - Dx[0] * Dz[1];
        float ngz = Dx[0] * Dy[1] - Dy[0] * Dx[1];
        float nng = sqrtf(ngx * ngx + ngy * ngy + ngz * ngz);
        if (nng == 0.0f) nng = EPS;
        float ig = 1.0f / nng;
        ngx *= ig; ngy *= ig; ngz *= ig;

        // pred normal
        float ax = Qx[1] - Qx[0], ay = Qy[1] - Qy[0], az = Qz[1] - Qz[0];
        float bx = Qx[2] - Qx[0], by = Qy[2] - Qy[0], bz = Qz[2] - Qz[0];
        float npx = ay * bz - az * by;
        float npy = az * bx - ax * bz;
        float npz = ax * by - ay * bx;
        float nnp = sqrtf(npx * npx + npy * npy + npz * npz);
        if (nnp == 0.0f) nnp = EPS;
        float ip = 1.0f / nnp;
        npx *= ip; npy *= ip; npz *= ip;

        float loss = fabsf(ngx - npx) + fabsf(ngy - npy) + fabsf(ngz - npz);

        float out = valid ? loss : INF_F;   // +inf sinks past all finite values
        g_loss[i] = out;
        if (valid) local_sum += loss;
        atomicAdd(&sh[__float_as_uint(out) >> 24], 1u);   // shared, privatized
    }

    // block reduction of valid-sum
    float s = local_sum;
    #pragma unroll
    for (int o = 16; o > 0; o >>= 1)
        s += __shfl_down_sync(0xffffffffu, s, o);
    int wid = threadIdx.x >> 5, lid = threadIdx.x & 31;
    if (lid == 0) sh_sum[wid] = s;
    __syncthreads();
    if (threadIdx.x == 0) {
        float ts = 0.0f;
        #pragma unroll
        for (int w = 0; w < 8; w++) ts += sh_sum[w];
        atomicAdd(&g_sum_valid, (double)ts);
    }
    unsigned int h = sh[threadIdx.x];
    if (h) atomicAdd(&g_hist8[threadIdx.x], h);

    // ---- last-block-done: resolve b8 without a separate launch ----
    __syncthreads();
    if (threadIdx.x == 0) {
        __threadfence();
        unsigned int v = atomicAdd(&g_done1, 1u);
        s_last = (v == (unsigned int)(gridDim.x - 1)) ? 1 : 0;
    }
    __syncthreads();
    if (!s_last) return;

    __threadfence();                      // make all blocks' writes visible
    __shared__ unsigned int rs[256];
    __shared__ unsigned int rs_n;
    int tt = threadIdx.x;
    unsigned int c = g_hist8[tt];
    if (tt == 0x7f) rs_n = NTOT - c;      // +inf has top8 = 0x7f; finite = valid
    rs[tt] = c;
    __syncthreads();

    #pragma unroll
    for (int o = 1; o < 256; o <<= 1) {
        unsigned int v = (tt >= o) ? rs[tt - o] : 0u;
        __syncthreads();
        rs[tt] += v;
        __syncthreads();
    }

    unsigned int n = rs_n;
    unsigned int k = n >> 2;              // drop n//4 smallest
    if (tt == 0) {
        g_n = n;
        g_done1 = 0u;                     // reset for next replay
        if (k == 0) { g_b8 = 0u; g_k1 = 0u; }
    }
    if (k > 0) {
        unsigned int below = (tt > 0) ? rs[tt - 1] : 0u;
        if (rs[tt] >= k && below < k) {   // exactly one thread fires
            g_b8 = (unsigned int)tt;
            g_k1 = k - below;
        }
    }
}

// ---------------- passC + fused finish in the last block ----------------
__global__ void __launch_bounds__(256)
passC_kernel(float* __restrict__ out)
{
    __shared__ unsigned int sh_c[256];
    __shared__ float        sh_f[256];
    __shared__ float        sh_b[8];
    __shared__ int          s_last;

    sh_c[threadIdx.x] = 0u;
    sh_f[threadIdx.x] = 0.0f;
    __syncthreads();

    unsigned int b8 = g_b8;
    float sb = 0.0f;

    int t = blockIdx.x * blockDim.x + threadIdx.x;
    const float4* L4 = reinterpret_cast<const float4*>(g_loss);

    float4 v[4];
    bool   ok[4];
    #pragma unroll
    for (int j = 0; j < 4; j++) {
        int q = t + j * PC_STRIDE;
        ok[j] = (q < NQUAD);
        v[j]  = L4[ok[j] ? q : 0];
    }

    #pragma unroll
    for (int j = 0; j < 4; j++) {
        if (!ok[j]) continue;
        float vs[4] = {v[j].x, v[j].y, v[j].z, v[j].w};
        #pragma unroll
        for (int e = 0; e < 4; e++) {
            float val = vs[e];
            unsigned int bits = __float_as_uint(val);
            unsigned int top = bits >> 24;
            if (top < b8) {
                sb += val;
            } else if (top == b8) {
                unsigned int bj = (bits >> 16) & 0xffu;
                atomicAdd(&sh_c[bj], 1u);
                atomicAdd(&sh_f[bj], val);
            }
        }
    }

    #pragma unroll
    for (int o = 16; o > 0; o >>= 1)
        sb += __shfl_down_sync(0xffffffffu, sb, o);
    int wid = threadIdx.x >> 5, lid = threadIdx.x & 31;
    if (lid == 0) sh_b[wid] = sb;
    __syncthreads();
    if (threadIdx.x == 0) {
        float tb = 0.0f;
        #pragma unroll
        for (int w = 0; w < 8; w++) tb += sh_b[w];
        atomicAdd(&g_sum_below, (double)tb);
    }
    unsigned int hc = sh_c[threadIdx.x];
    if (hc) {
        atomicAdd(&g_cnt2[threadIdx.x], hc);
        atomicAdd(&g_fsum2[threadIdx.x], sh_f[threadIdx.x]);
    }

    // ---- last-block-done: finish without a separate launch ----
    __syncthreads();
    if (threadIdx.x == 0) {
        __threadfence();
        unsigned int v = atomicAdd(&g_done2, 1u);
        s_last = (v == (unsigned int)(gridDim.x - 1)) ? 1 : 0;
    }
    __syncthreads();
    if (!s_last) return;

    __threadfence();
    __shared__ unsigned int s_scan[256];
    __shared__ float        s_f[256];
    __shared__ int          s_j;
    __shared__ unsigned int s_cum;
    __shared__ float        s_red[8];

    int tt = threadIdx.x;
    unsigned int c = g_cnt2[tt];
    float        fv = g_fsum2[tt];
    s_scan[tt] = c;
    s_f[tt]    = fv;
    if (tt == 0) { s_j = 0; s_cum = 0u; }
    __syncthreads();

    #pragma unroll
    for (int o = 1; o < 256; o <<= 1) {
        unsigned int v = (tt >= o) ? s_scan[tt - o] : 0u;
        __syncthreads();
        s_scan[tt] += v;
        __syncthreads();
    }

    unsigned int k1 = g_k1;
    if (k1 > 0) {
        unsigned int below = (tt > 0) ? s_scan[tt - 1] : 0u;
        if (s_scan[tt] >= k1 && below < k1) { s_j = tt; s_cum = below; }
    }
    __syncthreads();

    int j = s_j;
    float x = (tt < j) ? s_f[tt] : 0.0f;
    #pragma unroll
    for (int o = 16; o > 0; o >>= 1)
        x += __shfl_down_sync(0xffffffffu, x, o);
    if ((tt & 31) == 0) s_red[tt >> 5] = x;
    __syncthreads();

    if (tt == 0) {
        float sum_full = 0.0f;
        #pragma unroll
        for (int w = 0; w < 8; w++) sum_full += s_red[w];

        // partial bin priced at its lower edge (error << 1e-3 relative)
        float tf = __uint_as_float((g_b8 << 24) | ((unsigned int)j << 16));
        double sum_small = g_sum_below + (double)sum_full
                         + (double)(k1 - s_cum) * (double)tf;
        unsigned int n = g_n;
        long long d = (long long)n - (long long)(n >> 2);
        if (d < 1) d = 1;
        out[0] = (float)((g_sum_valid - sum_small) / (double)d);
    }
    __syncthreads();

    // reset all scratch so the next replay starts from zeros
    g_hist8[tt] = 0u;
    g_cnt2[tt]  = 0u;
    g_fsum2[tt] = 0.0f;
    if (tt == 0) {
        g_sum_valid = 0.0;
        g_sum_below = 0.0;
        g_done2     = 0u;
    }
}

// ---------------- launch ----------------
extern "C" void kernel_launch(void* const* d_in, const int* in_sizes, int n_in,
                              void* d_out, int out_size)
{
    const float* pred = (const float*)d_in[0];
    const float* tgt  = (const float*)d_in[1];
    // d_in[2] = mask (already baked into p1/p2/p3; unused)
    const float* intr = (const float*)d_in[3];
    const int*   p1   = (const int*)d_in[4];
    const int*   p2   = (const int*)d_in[5];
    const int*   p3   = (const int*)d_in[6];
    float* out = (float*)d_out;

    compute_kernel<<<CK_BLOCKS, 256>>>(pred, tgt, intr, p1, p2, p3);
    passC_kernel<<<PC_BLOCKS, 256>>>(out);
}